// round 5
// baseline (speedup 1.0000x reference)
#include <cuda_runtime.h>
#include <cstdint>

#define B_ 16
#define S_ 2048
#define D_ 128
#define SCALE_ 0.08838834764831845f  // 1/sqrt(128)

#define LDK_ 36    // 32-wide k tiles + 4 pad
#define LDN_ 132   // 128-wide n tiles + 4 pad (banks 8c+g for row-pair scalar loads)

// tf32 round (rna)
__device__ __forceinline__ uint32_t f2tf(float f) {
    uint32_t r;
    asm("cvt.rna.tf32.f32 %0, %1;" : "=r"(r) : "f"(f));
    return r;
}

// D += A*B, m16n8k8 tf32
__device__ __forceinline__ void mma8(float* d, uint32_t a0, uint32_t a1, uint32_t a2,
                                     uint32_t a3, uint32_t b0, uint32_t b1) {
    asm volatile(
        "mma.sync.aligned.m16n8k8.row.col.f32.tf32.tf32.f32 "
        "{%0,%1,%2,%3}, {%4,%5,%6,%7}, {%8,%9}, {%0,%1,%2,%3};"
        : "+f"(d[0]), "+f"(d[1]), "+f"(d[2]), "+f"(d[3])
        : "r"(a0), "r"(a1), "r"(a2), "r"(a3), "r"(b0), "r"(b1));
}

__device__ __forceinline__ uint32_t smem_u32(const void* p) {
    uint32_t a;
    asm("{ .reg .u64 t; cvta.to.shared.u64 t, %1; cvt.u32.u64 %0, t; }" : "=r"(a) : "l"(p));
    return a;
}

#define CPA16(dst, src) \
    asm volatile("cp.async.cg.shared.global [%0], [%1], 16;" :: "r"(dst), "l"(src))
#define CP_COMMIT() asm volatile("cp.async.commit_group;" ::: "memory")
#define CP_WAIT1()  asm volatile("cp.async.wait_group 1;" ::: "memory")

// =====================================================================
// Kernel 1: scores[b,q,k] = (Q.K^T)*SCALE + mask
// CTA 128x128, BK=32, 4 chunks, 3-stage cp.async pipeline.
// 8 warps = 2(m) x 4(n); warp tile 64x32. Pair (LDS.64) fragment loads.
// =====================================================================
#define S_STG 9216          // words per stage (Qs 4608 + Ks 4608)
#define S_SMEM (3 * S_STG * 4)

__global__ __launch_bounds__(256, 2) void scores_mma(
    const float* __restrict__ q, const float* __restrict__ k,
    const float* __restrict__ mask, float* __restrict__ attn)
{
    extern __shared__ float smem[];
    const uint32_t sb = smem_u32(smem);

    const int b  = blockIdx.x;
    const int kt = blockIdx.y * 128;
    const int qt = blockIdx.z * 128;

    const float* qb = q + ((size_t)b * S_ + qt) * D_;
    const float* kb = k + ((size_t)b * S_ + kt) * D_;

    const int tid  = threadIdx.x;
    const int wid  = tid >> 5, lane = tid & 31;
    const int g    = lane >> 2, c = lane & 3;
    const int wm   = (wid & 1) * 64;
    const int wn   = (wid >> 1) * 32;

    // prefetch coords (128 rows x 32 cols per matrix; 4 float4 per thread)
    const int pr[4] = { (tid) >> 3, (tid + 256) >> 3, (tid + 512) >> 3, (tid + 768) >> 3 };
    const int pc[4] = { ((tid) & 7) * 4, ((tid + 256) & 7) * 4,
                        ((tid + 512) & 7) * 4, ((tid + 768) & 7) * 4 };

    float acc[4][4][4];
#pragma unroll
    for (int mi = 0; mi < 4; mi++)
#pragma unroll
        for (int ni = 0; ni < 4; ni++)
#pragma unroll
            for (int r = 0; r < 4; r++) acc[mi][ni][r] = 0.0f;

    // prologue: prefetch chunks 0,1
#pragma unroll
    for (int chp = 0; chp < 2; chp++) {
        const uint32_t stb = sb + (uint32_t)chp * (S_STG * 4);
#pragma unroll
        for (int t = 0; t < 4; t++) {
            CPA16(stb + (uint32_t)(pr[t] * LDK_ + pc[t]) * 4,
                  qb + (size_t)pr[t] * D_ + chp * 32 + pc[t]);
            CPA16(stb + (uint32_t)(4608 + pr[t] * LDK_ + pc[t]) * 4,
                  kb + (size_t)pr[t] * D_ + chp * 32 + pc[t]);
        }
        CP_COMMIT();
    }

#pragma unroll 1
    for (int s = 0; s < 4; s++) {
        CP_WAIT1();
        __syncthreads();
        // prefetch chunk s+2 into stage (s+2)%3 (that stage was consumed at s-1)
        if (s + 2 < 4) {
            const int ch = s + 2;
            const uint32_t stb = sb + (uint32_t)((ch % 3) * S_STG * 4);
#pragma unroll
            for (int t = 0; t < 4; t++) {
                CPA16(stb + (uint32_t)(pr[t] * LDK_ + pc[t]) * 4,
                      qb + (size_t)pr[t] * D_ + ch * 32 + pc[t]);
                CPA16(stb + (uint32_t)(4608 + pr[t] * LDK_ + pc[t]) * 4,
                      kb + (size_t)pr[t] * D_ + ch * 32 + pc[t]);
            }
        }
        CP_COMMIT();

        const float* Qs = smem + (s % 3) * S_STG;
        const float* Ks = Qs + 4608;
#pragma unroll
        for (int kk = 0; kk < 4; kk++) {
            const int co = kk * 8 + 2 * c;
            uint32_t bf[4][2];
#pragma unroll
            for (int ni = 0; ni < 4; ni++) {
                const float2 bb = *(const float2*)&Ks[(wn + ni * 8 + g) * LDK_ + co];
                bf[ni][0] = f2tf(bb.x); bf[ni][1] = f2tf(bb.y);
            }
#pragma unroll
            for (int mi = 0; mi < 4; mi++) {
                const int row = wm + mi * 16 + g;
                const float2 a02 = *(const float2*)&Qs[row * LDK_ + co];
                const float2 a13 = *(const float2*)&Qs[(row + 8) * LDK_ + co];
                const uint32_t a0 = f2tf(a02.x), a2 = f2tf(a02.y);
                const uint32_t a1 = f2tf(a13.x), a3 = f2tf(a13.y);
#pragma unroll
                for (int ni = 0; ni < 4; ni++)
                    mma8(acc[mi][ni], a0, a1, a2, a3, bf[ni][0], bf[ni][1]);
            }
        }
    }

    // Epilogue: scale + mask
#pragma unroll
    for (int mi = 0; mi < 4; mi++) {
#pragma unroll
        for (int rr = 0; rr < 2; rr++) {
            const int qrow = qt + wm + mi * 16 + g + rr * 8;
            const float* mrow = mask + (size_t)qrow * S_ + kt;
            float* arow = attn + ((size_t)b * S_ + qrow) * S_ + kt;
#pragma unroll
            for (int ni = 0; ni < 4; ni++) {
                const int col = wn + ni * 8 + c * 2;
                const float2 m2 = *(const float2*)&mrow[col];
                float2 o;
                o.x = acc[mi][ni][rr * 2 + 0] * SCALE_ + m2.x;
                o.y = acc[mi][ni][rr * 2 + 1] * SCALE_ + m2.y;
                *(float2*)&arow[col] = o;
            }
        }
    }
}

// =====================================================================
// Kernel 2: in-place row softmax. One 256-thread CTA per row.
// =====================================================================
__global__ __launch_bounds__(256) void softmax_kernel(float* __restrict__ attn)
{
    __shared__ float red[256];
    const size_t row = blockIdx.x;
    float* p = attn + row * (size_t)S_;
    const int tid = threadIdx.x;

    float4 v0 = ((const float4*)p)[tid];
    float4 v1 = ((const float4*)p)[tid + 256];

    float m = fmaxf(fmaxf(fmaxf(v0.x, v0.y), fmaxf(v0.z, v0.w)),
                    fmaxf(fmaxf(v1.x, v1.y), fmaxf(v1.z, v1.w)));
    red[tid] = m;
    __syncthreads();
#pragma unroll
    for (int s = 128; s > 0; s >>= 1) {
        if (tid < s) red[tid] = fmaxf(red[tid], red[tid + s]);
        __syncthreads();
    }
    m = red[0];
    __syncthreads();

    v0.x = __expf(v0.x - m); v0.y = __expf(v0.y - m);
    v0.z = __expf(v0.z - m); v0.w = __expf(v0.w - m);
    v1.x = __expf(v1.x - m); v1.y = __expf(v1.y - m);
    v1.z = __expf(v1.z - m); v1.w = __expf(v1.w - m);

    float sum = (v0.x + v0.y) + (v0.z + v0.w) + (v1.x + v1.y) + (v1.z + v1.w);
    red[tid] = sum;
    __syncthreads();
#pragma unroll
    for (int s = 128; s > 0; s >>= 1) {
        if (tid < s) red[tid] += red[tid + s];
        __syncthreads();
    }
    const float inv = 1.0f / red[0];

    v0.x *= inv; v0.y *= inv; v0.z *= inv; v0.w *= inv;
    v1.x *= inv; v1.y *= inv; v1.z *= inv; v1.w *= inv;
    ((float4*)p)[tid]       = v0;
    ((float4*)p)[tid + 256] = v1;
}

// =====================================================================
// Kernel 3: out[b,q,d] = sum_s P[b,q,s] * V[b,s,d]
// CTA 128(q) x 128(d), K=2048 in 64 BK=32 chunks, 3-stage cp.async.
// =====================================================================
#define O_STG 8832          // words per stage (Ps 4608 + Vs 4224)
#define O_SMEM (3 * O_STG * 4)

__global__ __launch_bounds__(256, 2) void out_mma(
    const float* __restrict__ attn, const float* __restrict__ v,
    float* __restrict__ out)
{
    extern __shared__ float smem[];
    const uint32_t sb = smem_u32(smem);

    const int b  = blockIdx.x;
    const int qt = blockIdx.y * 128;

    const float* pb = attn + ((size_t)b * S_ + qt) * S_;
    const float* vb = v + (size_t)b * S_ * D_;

    const int tid  = threadIdx.x;
    const int wid  = tid >> 5, lane = tid & 31;
    const int g    = lane >> 2, c = lane & 3;
    const int wm   = (wid & 1) * 64;
    const int wn   = (wid >> 1) * 32;

    // P prefetch coords: 128 rows x 32 k (4 float4/thread)
    const int ppr[4] = { (tid) >> 3, (tid + 256) >> 3, (tid + 512) >> 3, (tid + 768) >> 3 };
    const int ppc[4] = { ((tid) & 7) * 4, ((tid + 256) & 7) * 4,
                         ((tid + 512) & 7) * 4, ((tid + 768) & 7) * 4 };
    // V prefetch coords: 32 rows x 128 d (4 float4/thread)
    const int vpr[4] = { (tid) >> 5, (tid + 256) >> 5, (tid + 512) >> 5, (tid + 768) >> 5 };
    const int vpc[4] = { ((tid) & 31) * 4, ((tid + 256) & 31) * 4,
                         ((tid + 512) & 31) * 4, ((tid + 768) & 31) * 4 };

    float acc[4][4][4];
#pragma unroll
    for (int mi = 0; mi < 4; mi++)
#pragma unroll
        for (int ni = 0; ni < 4; ni++)
#pragma unroll
            for (int r = 0; r < 4; r++) acc[mi][ni][r] = 0.0f;

    // prologue
#pragma unroll
    for (int chp = 0; chp < 2; chp++) {
        const uint32_t stb = sb + (uint32_t)chp * (O_STG * 4);
        const int k0 = chp * 32;
#pragma unroll
        for (int t = 0; t < 4; t++)
            CPA16(stb + (uint32_t)(ppr[t] * LDK_ + ppc[t]) * 4,
                  pb + (size_t)ppr[t] * S_ + k0 + ppc[t]);
#pragma unroll
        for (int t = 0; t < 4; t++)
            CPA16(stb + (uint32_t)(4608 + vpr[t] * LDN_ + vpc[t]) * 4,
                  vb + (size_t)(k0 + vpr[t]) * D_ + vpc[t]);
        CP_COMMIT();
    }

#pragma unroll 1
    for (int s = 0; s < 64; s++) {
        CP_WAIT1();
        __syncthreads();
        if (s + 2 < 64) {
            const int ch = s + 2, k0 = ch * 32;
            const uint32_t stb = sb + (uint32_t)((ch % 3) * O_STG * 4);
#pragma unroll
            for (int t = 0; t < 4; t++)
                CPA16(stb + (uint32_t)(ppr[t] * LDK_ + ppc[t]) * 4,
                      pb + (size_t)ppr[t] * S_ + k0 + ppc[t]);
#pragma unroll
            for (int t = 0; t < 4; t++)
                CPA16(stb + (uint32_t)(4608 + vpr[t] * LDN_ + vpc[t]) * 4,
                      vb + (size_t)(k0 + vpr[t]) * D_ + vpc[t]);
        }
        CP_COMMIT();

        const float* Ps = smem + (s % 3) * O_STG;
        const float* Vs = Ps + 4608;
#pragma unroll
        for (int kk = 0; kk < 4; kk++) {
            const int co = kk * 8 + 2 * c;
            uint32_t bf[4][2];
#pragma unroll
            for (int ni = 0; ni < 4; ni++) {
                const int col = wn + ni * 8 + g;
                bf[ni][0] = f2tf(Vs[(co)     * LDN_ + col]);
                bf[ni][1] = f2tf(Vs[(co + 1) * LDN_ + col]);
            }
#pragma unroll
            for (int mi = 0; mi < 4; mi++) {
                const int row = wm + mi * 16 + g;
                const float2 a02 = *(const float2*)&Ps[row * LDK_ + co];
                const float2 a13 = *(const float2*)&Ps[(row + 8) * LDK_ + co];
                const uint32_t a0 = f2tf(a02.x), a2 = f2tf(a02.y);
                const uint32_t a1 = f2tf(a13.x), a3 = f2tf(a13.y);
#pragma unroll
                for (int ni = 0; ni < 4; ni++)
                    mma8(acc[mi][ni], a0, a1, a2, a3, bf[ni][0], bf[ni][1]);
            }
        }
    }

#pragma unroll
    for (int mi = 0; mi < 4; mi++) {
#pragma unroll
        for (int rr = 0; rr < 2; rr++) {
            const int qrow = qt + wm + mi * 16 + g + rr * 8;
            float* orow = out + ((size_t)b * S_ + qrow) * D_;
#pragma unroll
            for (int ni = 0; ni < 4; ni++) {
                const int col = wn + ni * 8 + c * 2;
                float2 o = { acc[mi][ni][rr * 2 + 0], acc[mi][ni][rr * 2 + 1] };
                *(float2*)&orow[col] = o;
            }
        }
    }
}

// =====================================================================
// d_out = [output (B*S*D) | attn (B*S*S)]
// =====================================================================
extern "C" void kernel_launch(void* const* d_in, const int* in_sizes, int n_in,
                              void* d_out, int out_size)
{
    const float* q    = (const float*)d_in[0];
    const float* k    = (const float*)d_in[1];
    const float* v    = (const float*)d_in[2];
    const float* mask = (const float*)d_in[3];

    float* out  = (float*)d_out;
    float* attn = out + (size_t)B_ * S_ * D_;

    static int configured = 0;
    if (!configured) {
        cudaFuncSetAttribute(scores_mma, cudaFuncAttributeMaxDynamicSharedMemorySize, S_SMEM);
        cudaFuncSetAttribute(out_mma,    cudaFuncAttributeMaxDynamicSharedMemorySize, O_SMEM);
        configured = 1;
    }

    dim3 g1(B_, S_ / 128, S_ / 128);   // b fastest -> L2 reuse of Q/K/mask tiles
    scores_mma<<<g1, 256, S_SMEM>>>(q, k, mask, attn);

    softmax_kernel<<<B_ * S_, 256>>>(attn);

    dim3 g3(B_, S_ / 128);
    out_mma<<<g3, 256, O_SMEM>>>(attn, v, out);
}

// round 6
// speedup vs baseline: 1.0285x; 1.0285x over previous
#include <cuda_runtime.h>
#include <cstdint>

#define B_ 16
#define S_ 2048
#define D_ 128
#define SCALE_ 0.08838834764831845f  // 1/sqrt(128)

// tf32 round (rna)
__device__ __forceinline__ uint32_t f2tf(float f) {
    uint32_t r;
    asm("cvt.rna.tf32.f32 %0, %1;" : "=r"(r) : "f"(f));
    return r;
}

// D += A*B, m16n8k8 tf32
__device__ __forceinline__ void mma8(float* d, uint32_t a0, uint32_t a1, uint32_t a2,
                                     uint32_t a3, uint32_t b0, uint32_t b1) {
    asm volatile(
        "mma.sync.aligned.m16n8k8.row.col.f32.tf32.tf32.f32 "
        "{%0,%1,%2,%3}, {%4,%5,%6,%7}, {%8,%9}, {%0,%1,%2,%3};"
        : "+f"(d[0]), "+f"(d[1]), "+f"(d[2]), "+f"(d[3])
        : "r"(a0), "r"(a1), "r"(a2), "r"(a3), "r"(b0), "r"(b1));
}

// =====================================================================
// Kernel 1: scores[b,q,k] = (Q.K^T)*SCALE + mask
// CTA 128x128, BK=32. 8 warps = 2(m) x 4(n); warp tile 64x32.
// k-remap: thread c holds k in {4c..4c+3}  ->  every fragment load is
// one LDS.128. Smem stride 48 words (mod 32 == 16) -> conflict-free.
// =====================================================================
#define SLD_ 48
#define S_SMEM (2 * 128 * SLD_ * 4)   // Qs + Ks, 49152 B

__global__ __launch_bounds__(256, 2) void scores_mma(
    const float* __restrict__ q, const float* __restrict__ k,
    const float* __restrict__ mask, float* __restrict__ attn)
{
    extern __shared__ uint32_t smem[];
    uint32_t* Qs = smem;                 // [128][SLD_]
    uint32_t* Ks = smem + 128 * SLD_;    // [128][SLD_]

    const int b  = blockIdx.x;
    const int kt = blockIdx.y * 128;
    const int qt = blockIdx.z * 128;

    const float* qb = q + ((size_t)b * S_ + qt) * D_;
    const float* kb = k + ((size_t)b * S_ + kt) * D_;

    const int tid  = threadIdx.x;
    const int wid  = tid >> 5, lane = tid & 31;
    const int g    = lane >> 2, c = lane & 3;
    const int wm   = (wid & 1) * 64;
    const int wn   = (wid >> 1) * 32;

    float acc[4][4][4];
#pragma unroll
    for (int mi = 0; mi < 4; mi++)
#pragma unroll
        for (int ni = 0; ni < 4; ni++)
#pragma unroll
            for (int r = 0; r < 4; r++) acc[mi][ni][r] = 0.0f;

#pragma unroll 1
    for (int d0 = 0; d0 < D_; d0 += 32) {
        // Fill 128x32 chunks of Q and K (tf32-rounded at fill).
#pragma unroll
        for (int t = 0; t < 4; t++) {
            const int idx = tid + t * 256;
            const int row = idx >> 3, c4 = (idx & 7) * 4;
            const float4 vq = *(const float4*)&qb[(size_t)row * D_ + d0 + c4];
            const float4 vk = *(const float4*)&kb[(size_t)row * D_ + d0 + c4];
            uint4 uq = { f2tf(vq.x), f2tf(vq.y), f2tf(vq.z), f2tf(vq.w) };
            uint4 uk = { f2tf(vk.x), f2tf(vk.y), f2tf(vk.z), f2tf(vk.w) };
            *(uint4*)&Qs[row * SLD_ + c4] = uq;
            *(uint4*)&Ks[row * SLD_ + c4] = uk;
        }
        __syncthreads();

#pragma unroll
        for (int kq = 0; kq < 2; kq++) {      // 16-k groups
            const int co = kq * 16 + 4 * c;
            uint4 bf[4];
#pragma unroll
            for (int ni = 0; ni < 4; ni++)
                bf[ni] = *(const uint4*)&Ks[(wn + ni * 8 + g) * SLD_ + co];
#pragma unroll
            for (int mi = 0; mi < 4; mi++) {
                const int row = wm + mi * 16 + g;
                const uint4 q0 = *(const uint4*)&Qs[row * SLD_ + co];
                const uint4 q1 = *(const uint4*)&Qs[(row + 8) * SLD_ + co];
#pragma unroll
                for (int ni = 0; ni < 4; ni++) {
                    mma8(acc[mi][ni], q0.x, q1.x, q0.y, q1.y, bf[ni].x, bf[ni].y);
                    mma8(acc[mi][ni], q0.z, q1.z, q0.w, q1.w, bf[ni].z, bf[ni].w);
                }
            }
        }
        __syncthreads();
    }

    // Epilogue: scale + mask
#pragma unroll
    for (int mi = 0; mi < 4; mi++) {
#pragma unroll
        for (int rr = 0; rr < 2; rr++) {
            const int qrow = qt + wm + mi * 16 + g + rr * 8;
            const float* mrow = mask + (size_t)qrow * S_ + kt;
            float* arow = attn + ((size_t)b * S_ + qrow) * S_ + kt;
#pragma unroll
            for (int ni = 0; ni < 4; ni++) {
                const int col = wn + ni * 8 + c * 2;
                const float2 m2 = *(const float2*)&mrow[col];
                float2 o;
                o.x = acc[mi][ni][rr * 2 + 0] * SCALE_ + m2.x;
                o.y = acc[mi][ni][rr * 2 + 1] * SCALE_ + m2.y;
                *(float2*)&arow[col] = o;
            }
        }
    }
}

// =====================================================================
// Kernel 2: in-place row softmax. One 256-thread CTA per row.
// =====================================================================
__global__ __launch_bounds__(256) void softmax_kernel(float* __restrict__ attn)
{
    __shared__ float red[256];
    const size_t row = blockIdx.x;
    float* p = attn + row * (size_t)S_;
    const int tid = threadIdx.x;

    float4 v0 = ((const float4*)p)[tid];
    float4 v1 = ((const float4*)p)[tid + 256];

    float m = fmaxf(fmaxf(fmaxf(v0.x, v0.y), fmaxf(v0.z, v0.w)),
                    fmaxf(fmaxf(v1.x, v1.y), fmaxf(v1.z, v1.w)));
    red[tid] = m;
    __syncthreads();
#pragma unroll
    for (int s = 128; s > 0; s >>= 1) {
        if (tid < s) red[tid] = fmaxf(red[tid], red[tid + s]);
        __syncthreads();
    }
    m = red[0];
    __syncthreads();

    v0.x = __expf(v0.x - m); v0.y = __expf(v0.y - m);
    v0.z = __expf(v0.z - m); v0.w = __expf(v0.w - m);
    v1.x = __expf(v1.x - m); v1.y = __expf(v1.y - m);
    v1.z = __expf(v1.z - m); v1.w = __expf(v1.w - m);

    float sum = (v0.x + v0.y) + (v0.z + v0.w) + (v1.x + v1.y) + (v1.z + v1.w);
    red[tid] = sum;
    __syncthreads();
#pragma unroll
    for (int s = 128; s > 0; s >>= 1) {
        if (tid < s) red[tid] += red[tid + s];
        __syncthreads();
    }
    const float inv = 1.0f / red[0];

    v0.x *= inv; v0.y *= inv; v0.z *= inv; v0.w *= inv;
    v1.x *= inv; v1.y *= inv; v1.z *= inv; v1.w *= inv;
    ((float4*)p)[tid]       = v0;
    ((float4*)p)[tid + 256] = v1;
}

// =====================================================================
// Kernel 3: out[b,q,d] = sum_s P[b,q,s] * V[b,s,d]   (round-4 verbatim)
// CTA 128(q) x 128(d), K=2048 in BK=32 chunks. V natural layout = [k][n].
// =====================================================================
#define LDK_ 36
#define LDN_ 136

__global__ __launch_bounds__(256, 2) void out_mma(
    const float* __restrict__ attn, const float* __restrict__ v,
    float* __restrict__ out)
{
    __shared__ float Ps[128][LDK_];   // [m][k]
    __shared__ float Vs[32][LDN_];    // [k][n]

    const int b  = blockIdx.x;
    const int qt = blockIdx.y * 128;

    const float* pb = attn + ((size_t)b * S_ + qt) * S_;
    const float* vb = v + (size_t)b * S_ * D_;

    const int tid  = threadIdx.x;
    const int wid  = tid >> 5, lane = tid & 31;
    const int g    = lane >> 2, c = lane & 3;
    const int wm   = (wid & 1) * 64;
    const int wn   = (wid >> 1) * 32;

    float acc[4][4][4];
#pragma unroll
    for (int mi = 0; mi < 4; mi++)
#pragma unroll
        for (int ni = 0; ni < 4; ni++)
#pragma unroll
            for (int r = 0; r < 4; r++) acc[mi][ni][r] = 0.0f;

#pragma unroll 1
    for (int k0 = 0; k0 < S_; k0 += 32) {
#pragma unroll
        for (int t = 0; t < 4; t++) {
            const int idx = tid + t * 256;
            const int row = idx >> 3, c4 = (idx & 7) * 4;
            const float4 vp = *(const float4*)&pb[(size_t)row * S_ + k0 + c4];
            uint4 up = { f2tf(vp.x), f2tf(vp.y), f2tf(vp.z), f2tf(vp.w) };
            *(uint4*)&Ps[row][c4] = up;
        }
#pragma unroll
        for (int t = 0; t < 4; t++) {
            const int idx = tid + t * 256;
            const int row = idx >> 5, c4 = (idx & 31) * 4;
            const float4 vv = *(const float4*)&vb[(size_t)(k0 + row) * D_ + c4];
            uint4 uv = { f2tf(vv.x), f2tf(vv.y), f2tf(vv.z), f2tf(vv.w) };
            *(uint4*)&Vs[row][c4] = uv;
        }
        __syncthreads();

#pragma unroll
        for (int kk = 0; kk < 4; kk++) {
            const int co = kk * 8;
            uint32_t bf[4][2];
#pragma unroll
            for (int ni = 0; ni < 4; ni++) {
                const int col = wn + ni * 8 + g;
                bf[ni][0] = __float_as_uint(Vs[co + c][col]);
                bf[ni][1] = __float_as_uint(Vs[co + c + 4][col]);
            }
#pragma unroll
            for (int mi = 0; mi < 4; mi++) {
                const int row = wm + mi * 16 + g;
                const uint32_t a0 = __float_as_uint(Ps[row][co + c]);
                const uint32_t a1 = __float_as_uint(Ps[row + 8][co + c]);
                const uint32_t a2 = __float_as_uint(Ps[row][co + c + 4]);
                const uint32_t a3 = __float_as_uint(Ps[row + 8][co + c + 4]);
#pragma unroll
                for (int ni = 0; ni < 4; ni++)
                    mma8(acc[mi][ni], a0, a1, a2, a3, bf[ni][0], bf[ni][1]);
            }
        }
        __syncthreads();
    }

#pragma unroll
    for (int mi = 0; mi < 4; mi++) {
#pragma unroll
        for (int rr = 0; rr < 2; rr++) {
            const int qrow = qt + wm + mi * 16 + g + rr * 8;
            float* orow = out + ((size_t)b * S_ + qrow) * D_;
#pragma unroll
            for (int ni = 0; ni < 4; ni++) {
                const int col = wn + ni * 8 + c * 2;
                float2 o = { acc[mi][ni][rr * 2 + 0], acc[mi][ni][rr * 2 + 1] };
                *(float2*)&orow[col] = o;
            }
        }
    }
}

// =====================================================================
// d_out = [output (B*S*D) | attn (B*S*S)]
// =====================================================================
extern "C" void kernel_launch(void* const* d_in, const int* in_sizes, int n_in,
                              void* d_out, int out_size)
{
    const float* q    = (const float*)d_in[0];
    const float* k    = (const float*)d_in[1];
    const float* v    = (const float*)d_in[2];
    const float* mask = (const float*)d_in[3];

    float* out  = (float*)d_out;
    float* attn = out + (size_t)B_ * S_ * D_;

    cudaFuncSetAttribute(scores_mma, cudaFuncAttributeMaxDynamicSharedMemorySize, S_SMEM);

    dim3 g1(B_, S_ / 128, S_ / 128);   // b fastest -> L2 reuse of Q/K/mask tiles
    scores_mma<<<g1, 256, S_SMEM>>>(q, k, mask, attn);

    softmax_kernel<<<B_ * S_, 256>>>(attn);

    dim3 g3(B_, S_ / 128);
    out_mma<<<g3, 256>>>(attn, v, out);
}

// round 8
// speedup vs baseline: 1.2740x; 1.2387x over previous
#include <cuda_runtime.h>
#include <cuda_fp16.h>
#include <cstdint>

#define B_ 16
#define S_ 2048
#define D_ 128
#define SCALE_ 0.08838834764831845f  // 1/sqrt(128)

#define HLD_ 48    // halves per smem row (32 data + 16 pad) = 24 words
#define VLD_ 136   // words per Vs2 row (128 data + 8 pad)

__device__ __forceinline__ uint32_t h2u(half2 h) {
    union { half2 h; uint32_t u; } cvt;
    cvt.h = h;
    return cvt.u;
}

// D += A*B, m16n8k16 f16 (f32 accum)
__device__ __forceinline__ void mma16(float* d, uint32_t a0, uint32_t a1, uint32_t a2,
                                      uint32_t a3, uint32_t b0, uint32_t b1) {
    asm volatile(
        "mma.sync.aligned.m16n8k16.row.col.f32.f16.f16.f32 "
        "{%0,%1,%2,%3}, {%4,%5,%6,%7}, {%8,%9}, {%0,%1,%2,%3};"
        : "+f"(d[0]), "+f"(d[1]), "+f"(d[2]), "+f"(d[3])
        : "r"(a0), "r"(a1), "r"(a2), "r"(a3), "r"(b0), "r"(b1));
}

// Store float4 (k-offsets c4..c4+3 of a 32-wide chunk row) into the permuted
// half layout: within each 16-k group, k = 2c+h+8e is stored at pos 4c+2e+h.
// A float4 at c4 (multiple of 4) maps to half2 at pos and half2 at pos+4.
__device__ __forceinline__ void store_perm(half* rowp, int c4, float4 v) {
    const int kk0 = c4 & 15;
    const int pos = ((c4 >> 4) << 4) + ((kk0 & 7) << 1) + ((kk0 >> 3) << 1);
    *(half2*)(rowp + pos)     = __floats2half2_rn(v.x, v.y);
    *(half2*)(rowp + pos + 4) = __floats2half2_rn(v.z, v.w);
}

// =====================================================================
// Kernel 1: scores[b,q,k] = (Q.K^T)*SCALE + mask
// CTA 128x128, BK=32. 8 warps = 2(m) x 4(n); warp tile 64x32.
// fp16 m16n8k16, permuted-k smem: every fragment = one LDS.64.
// =====================================================================
__global__ __launch_bounds__(256, 2) void scores_mma(
    const float* __restrict__ q, const float* __restrict__ k,
    const float* __restrict__ mask, float* __restrict__ attn)
{
    __shared__ half Qh[128 * HLD_];
    __shared__ half Kh[128 * HLD_];

    const int b  = blockIdx.x;
    const int kt = blockIdx.y * 128;
    const int qt = blockIdx.z * 128;

    const float* qb = q + ((size_t)b * S_ + qt) * D_;
    const float* kb = k + ((size_t)b * S_ + kt) * D_;

    const int tid  = threadIdx.x;
    const int wid  = tid >> 5, lane = tid & 31;
    const int g    = lane >> 2, c = lane & 3;
    const int wm   = (wid & 1) * 64;
    const int wn   = (wid >> 1) * 32;

    float acc[4][4][4];
#pragma unroll
    for (int mi = 0; mi < 4; mi++)
#pragma unroll
        for (int ni = 0; ni < 4; ni++)
#pragma unroll
            for (int r = 0; r < 4; r++) acc[mi][ni][r] = 0.0f;

#pragma unroll 1
    for (int d0 = 0; d0 < D_; d0 += 32) {
#pragma unroll
        for (int t = 0; t < 4; t++) {
            const int idx = tid + t * 256;
            const int row = idx >> 3, c4 = (idx & 7) * 4;
            const float4 vq = *(const float4*)&qb[(size_t)row * D_ + d0 + c4];
            const float4 vk = *(const float4*)&kb[(size_t)row * D_ + d0 + c4];
            store_perm(&Qh[row * HLD_], c4, vq);
            store_perm(&Kh[row * HLD_], c4, vk);
        }
        __syncthreads();

#pragma unroll
        for (int kq = 0; kq < 2; kq++) {
            const int co = kq * 16 + 4 * c;
            uint2 bf[4];
#pragma unroll
            for (int ni = 0; ni < 4; ni++)
                bf[ni] = *(const uint2*)&Kh[(wn + ni * 8 + g) * HLD_ + co];
#pragma unroll
            for (int mi = 0; mi < 4; mi++) {
                const int row = wm + mi * 16 + g;
                const uint2 alo = *(const uint2*)&Qh[row * HLD_ + co];
                const uint2 ahi = *(const uint2*)&Qh[(row + 8) * HLD_ + co];
#pragma unroll
                for (int ni = 0; ni < 4; ni++)
                    mma16(acc[mi][ni], alo.x, ahi.x, alo.y, ahi.y, bf[ni].x, bf[ni].y);
            }
        }
        __syncthreads();
    }

    // Epilogue: scale + mask
#pragma unroll
    for (int mi = 0; mi < 4; mi++) {
#pragma unroll
        for (int rr = 0; rr < 2; rr++) {
            const int qrow = qt + wm + mi * 16 + g + rr * 8;
            const float* mrow = mask + (size_t)qrow * S_ + kt;
            float* arow = attn + ((size_t)b * S_ + qrow) * S_ + kt;
#pragma unroll
            for (int ni = 0; ni < 4; ni++) {
                const int col = wn + ni * 8 + c * 2;
                const float2 m2 = *(const float2*)&mrow[col];
                float2 o;
                o.x = acc[mi][ni][rr * 2 + 0] * SCALE_ + m2.x;
                o.y = acc[mi][ni][rr * 2 + 1] * SCALE_ + m2.y;
                *(float2*)&arow[col] = o;
            }
        }
    }
}

// =====================================================================
// Kernel 2: in-place row softmax. One 256-thread CTA per row.
// =====================================================================
__global__ __launch_bounds__(256) void softmax_kernel(float* __restrict__ attn)
{
    __shared__ float red[256];
    const size_t row = blockIdx.x;
    float* p = attn + row * (size_t)S_;
    const int tid = threadIdx.x;

    float4 v0 = ((const float4*)p)[tid];
    float4 v1 = ((const float4*)p)[tid + 256];

    float m = fmaxf(fmaxf(fmaxf(v0.x, v0.y), fmaxf(v0.z, v0.w)),
                    fmaxf(fmaxf(v1.x, v1.y), fmaxf(v1.z, v1.w)));
    red[tid] = m;
    __syncthreads();
#pragma unroll
    for (int s = 128; s > 0; s >>= 1) {
        if (tid < s) red[tid] = fmaxf(red[tid], red[tid + s]);
        __syncthreads();
    }
    m = red[0];
    __syncthreads();

    v0.x = __expf(v0.x - m); v0.y = __expf(v0.y - m);
    v0.z = __expf(v0.z - m); v0.w = __expf(v0.w - m);
    v1.x = __expf(v1.x - m); v1.y = __expf(v1.y - m);
    v1.z = __expf(v1.z - m); v1.w = __expf(v1.w - m);

    float sum = (v0.x + v0.y) + (v0.z + v0.w) + (v1.x + v1.y) + (v1.z + v1.w);
    red[tid] = sum;
    __syncthreads();
#pragma unroll
    for (int s = 128; s > 0; s >>= 1) {
        if (tid < s) red[tid] += red[tid + s];
        __syncthreads();
    }
    const float inv = 1.0f / red[0];

    v0.x *= inv; v0.y *= inv; v0.z *= inv; v0.w *= inv;
    v1.x *= inv; v1.y *= inv; v1.z *= inv; v1.w *= inv;
    ((float4*)p)[tid]       = v0;
    ((float4*)p)[tid + 256] = v1;
}

// =====================================================================
// Kernel 3: out[b,q,d] = sum_s P[b,q,s] * V[b,s,d]
// fp16 m16n8k16. P permuted like Q; V packed as half2 k-pairs:
// Vs2[pair][n] = half2(V[2p][n], V[2p+1][n])  ->  B frag = one LDS.32.
// =====================================================================
__global__ __launch_bounds__(256, 2) void out_mma(
    const float* __restrict__ attn, const float* __restrict__ v,
    float* __restrict__ out)
{
    __shared__ half Ph[128 * HLD_];
    __shared__ uint32_t Vs2[16 * VLD_];

    const int b  = blockIdx.x;
    const int qt = blockIdx.y * 128;

    const float* pb = attn + ((size_t)b * S_ + qt) * S_;
    const float* vb = v + (size_t)b * S_ * D_;

    const int tid  = threadIdx.x;
    const int wid  = tid >> 5, lane = tid & 31;
    const int g    = lane >> 2, c = lane & 3;
    const int wm   = (wid & 1) * 64;
    const int wn   = (wid >> 1) * 32;

    const int pr    = tid >> 4;         // pair row 0..15 (k pair 2pr,2pr+1)
    const int dbase = (tid & 15) * 4;   // d 0..60, second region +64

    float acc[4][4][4];
#pragma unroll
    for (int mi = 0; mi < 4; mi++)
#pragma unroll
        for (int ni = 0; ni < 4; ni++)
#pragma unroll
            for (int r = 0; r < 4; r++) acc[mi][ni][r] = 0.0f;

#pragma unroll 1
    for (int k0 = 0; k0 < S_; k0 += 32) {
        // P fill (permuted halves)
#pragma unroll
        for (int t = 0; t < 4; t++) {
            const int idx = tid + t * 256;
            const int row = idx >> 3, c4 = (idx & 7) * 4;
            const float4 vp = *(const float4*)&pb[(size_t)row * S_ + k0 + c4];
            store_perm(&Ph[row * HLD_], c4, vp);
        }
        // V fill: pack k-pairs into half2
        {
            const float* v0r = vb + (size_t)(k0 + 2 * pr) * D_;
            const float* v1r = v0r + D_;
#pragma unroll
            for (int h = 0; h < 2; h++) {
                const int d = dbase + h * 64;
                const float4 a = *(const float4*)&v0r[d];
                const float4 bb = *(const float4*)&v1r[d];
                uint4 u;
                u.x = h2u(__floats2half2_rn(a.x, bb.x));
                u.y = h2u(__floats2half2_rn(a.y, bb.y));
                u.z = h2u(__floats2half2_rn(a.z, bb.z));
                u.w = h2u(__floats2half2_rn(a.w, bb.w));
                *(uint4*)&Vs2[pr * VLD_ + d] = u;
            }
        }
        __syncthreads();

#pragma unroll
        for (int kq = 0; kq < 2; kq++) {
            const int co = kq * 16 + 4 * c;
            uint32_t bf[4][2];
#pragma unroll
            for (int ni = 0; ni < 4; ni++) {
                const int col = wn + ni * 8 + g;
                bf[ni][0] = Vs2[(kq * 8 + c)     * VLD_ + col];
                bf[ni][1] = Vs2[(kq * 8 + c + 4) * VLD_ + col];
            }
#pragma unroll
            for (int mi = 0; mi < 4; mi++) {
                const int row = wm + mi * 16 + g;
                const uint2 alo = *(const uint2*)&Ph[row * HLD_ + co];
                const uint2 ahi = *(const uint2*)&Ph[(row + 8) * HLD_ + co];
#pragma unroll
                for (int ni = 0; ni < 4; ni++)
                    mma16(acc[mi][ni], alo.x, ahi.x, alo.y, ahi.y, bf[ni][0], bf[ni][1]);
            }
        }
        __syncthreads();
    }

#pragma unroll
    for (int mi = 0; mi < 4; mi++) {
#pragma unroll
        for (int rr = 0; rr < 2; rr++) {
            const int qrow = qt + wm + mi * 16 + g + rr * 8;
            float* orow = out + ((size_t)b * S_ + qrow) * D_;
#pragma unroll
            for (int ni = 0; ni < 4; ni++) {
                const int col = wn + ni * 8 + c * 2;
                float2 o = { acc[mi][ni][rr * 2 + 0], acc[mi][ni][rr * 2 + 1] };
                *(float2*)&orow[col] = o;
            }
        }
    }
}

// =====================================================================
// d_out = [output (B*S*D) | attn (B*S*S)]
// =====================================================================
extern "C" void kernel_launch(void* const* d_in, const int* in_sizes, int n_in,
                              void* d_out, int out_size)
{
    const float* q    = (const float*)d_in[0];
    const float* k    = (const float*)d_in[1];
    const float* v    = (const float*)d_in[2];
    const float* mask = (const float*)d_in[3];

    float* out  = (float*)d_out;
    float* attn = out + (size_t)B_ * S_ * D_;

    dim3 g1(B_, S_ / 128, S_ / 128);   // b fastest -> L2 reuse of Q/K/mask tiles
    scores_mma<<<g1, 256>>>(q, k, mask, attn);

    softmax_kernel<<<B_ * S_, 256>>>(attn);

    dim3 g3(B_, S_ / 128);
    out_mma<<<g3, 256>>>(attn, v, out);
}